// round 2
// baseline (speedup 1.0000x reference)
#include <cuda_runtime.h>
#include <math.h>
#include <float.h>

#define BB 8
#define NS 300
#define NT 100
#define CC 512
// JV on transposed problem: N rows (targets), M cols (sources)
#define JV_N NT
#define JV_M NS
#define K_SLOTS 10            // ceil(300/32)

__device__ float g_lse[BB * NS];
__device__ float g_cost[BB * NT * NS];   // [b][t][s]

// ---------------------------------------------------------------------------
// Kernel 1: logsumexp over class dim, one warp per (b,s) row.
// grid = 300 blocks x 256 threads (8 warps); warp w -> row blockIdx*8+w.
// ---------------------------------------------------------------------------
__global__ void lse_kernel(const float* __restrict__ logits) {
    int warp = threadIdx.x >> 5;
    int lane = threadIdx.x & 31;
    int row  = blockIdx.x * 8 + warp;          // < 2400
    const float4* x = (const float4*)(logits + (size_t)row * CC);

    float4 a = x[lane];
    float4 b = x[lane + 32];
    float4 c = x[lane + 64];
    float4 d = x[lane + 96];

    float m = fmaxf(fmaxf(fmaxf(a.x, a.y), fmaxf(a.z, a.w)),
                    fmaxf(fmaxf(b.x, b.y), fmaxf(b.z, b.w)));
    m = fmaxf(m, fmaxf(fmaxf(fmaxf(c.x, c.y), fmaxf(c.z, c.w)),
                       fmaxf(fmaxf(d.x, d.y), fmaxf(d.z, d.w))));
    #pragma unroll
    for (int o = 16; o > 0; o >>= 1)
        m = fmaxf(m, __shfl_xor_sync(0xffffffffu, m, o));

    float s = expf(a.x - m) + expf(a.y - m) + expf(a.z - m) + expf(a.w - m)
            + expf(b.x - m) + expf(b.y - m) + expf(b.z - m) + expf(b.w - m)
            + expf(c.x - m) + expf(c.y - m) + expf(c.z - m) + expf(c.w - m)
            + expf(d.x - m) + expf(d.y - m) + expf(d.z - m) + expf(d.w - m);
    #pragma unroll
    for (int o = 16; o > 0; o >>= 1)
        s += __shfl_xor_sync(0xffffffffu, s, o);

    if (lane == 0) g_lse[row] = m + logf(s);
}

// ---------------------------------------------------------------------------
// Kernel 2: pairwise cost  cost[b][t][s] = CE + 10*(1-GIOU) + L1
// ---------------------------------------------------------------------------
__global__ void cost_kernel(const float* __restrict__ logits,
                            const float* __restrict__ sb,
                            const float* __restrict__ tb,
                            const int*   __restrict__ tgt) {
    int t = blockIdx.x;
    int b = blockIdx.y;
    int s = threadIdx.x;
    if (s >= NS) return;

    int cls = tgt[b * NT + t];
    float lse = g_lse[b * NS + s];
    float lg  = logits[((size_t)(b * NS + s)) * CC + cls];
    float ce  = lse - lg;

    const float4 av = *(const float4*)(sb + ((size_t)(b * NS + s)) * 4);
    const float4 bv = *(const float4*)(tb + ((size_t)(b * NT + t)) * 4);
    float ax1 = av.x, ay1 = av.y, ax2 = av.z, ay2 = av.w;
    float bx1 = bv.x, by1 = bv.y, bx2 = bv.z, by2 = bv.w;

    float l1 = 0.25f * (fabsf(ax1 - bx1) + fabsf(ay1 - by1) +
                        fabsf(ax2 - bx2) + fabsf(ay2 - by2));

    float ix1 = fmaxf(ax1, bx1), iy1 = fmaxf(ay1, by1);
    float ix2 = fminf(ax2, bx2), iy2 = fminf(ay2, by2);
    float inter = fmaxf(ix2 - ix1, 0.f) * fmaxf(iy2 - iy1, 0.f);
    float aa = (ax2 - ax1) * (ay2 - ay1);
    float ab = (bx2 - bx1) * (by2 - by1);
    float un = aa + ab - inter;
    float iou = inter / un;
    float ex1 = fminf(ax1, bx1), ey1 = fminf(ay1, by1);
    float ex2 = fmaxf(ax2, bx2), ey2 = fmaxf(ay2, by2);
    float encl = (ex2 - ex1) * (ey2 - ey1);
    float giou = iou - (encl - un) / encl;

    g_cost[(b * NT + t) * NS + s] = ce + 10.f * (1.f - giou) + l1;
}

// ---------------------------------------------------------------------------
// Kernel 3: single-warp Jonker-Volgenant (deferred dual updates) per batch.
// Lane L owns columns j = k*32 + L, k = 0..9.  v / SP / used live in REGISTERS.
// SMEM: cost matrix (fp32), p[300] (0 = free, else row+1), way[300], u[100].
// ---------------------------------------------------------------------------
#define JV_SMEM_BYTES (JV_N * JV_M * 4 + JV_N * 4 + JV_M * 4 * 2)

__global__ void __launch_bounds__(32, 1)
hungarian_kernel(float* __restrict__ out) {
    const int b    = blockIdx.x;
    const int lane = threadIdx.x;
    const float INF = __int_as_float(0x7f800000);

    extern __shared__ unsigned char raw[];
    float* sc  = (float*)raw;                 // [100][300]
    float* u   = sc + JV_N * JV_M;            // [100]
    int*   p   = (int*)(u + JV_N);            // [300]
    int*   way = p + JV_M;                    // [300]

    const float* gc = g_cost + (size_t)b * JV_N * JV_M;
    for (int t = lane; t < JV_N * JV_M; t += 32) sc[t] = gc[t];
    for (int t = lane; t < JV_N; t += 32) u[t] = 0.f;
    for (int t = lane; t < JV_M; t += 32) p[t] = 0;
    __syncwarp();

    float v_r[K_SLOTS];
    float SP [K_SLOTS];
    #pragma unroll
    for (int k = 0; k < K_SLOTS; ++k) v_r[k] = 0.f;

    for (int i = 0; i < JV_N; ++i) {
        #pragma unroll
        for (int k = 0; k < K_SLOTS; ++k) SP[k] = INF;
        unsigned usedmask = 0;
        int   i0     = i;
        int   j0prev = -1;
        float minval = 0.f;
        int   j1     = -1;

        while (true) {
            float ui0 = u[i0];                       // broadcast LDS
            const float* row = sc + i0 * JV_M;
            float base = minval - ui0;

            float bestval = INF;
            int   bestk   = 0;
            #pragma unroll
            for (int k = 0; k < K_SLOTS; ++k) {
                int j = k * 32 + lane;
                if (j < JV_M && !((usedmask >> k) & 1u)) {
                    float r = base + row[j] - v_r[k];
                    if (r < SP[k]) { SP[k] = r; way[j] = j0prev; }
                    if (SP[k] < bestval) { bestval = SP[k]; bestk = k; }
                }
            }

            // warp argmin: single REDUX on a total-order key, then ballot.
            unsigned bits = __float_as_uint(bestval);
            unsigned key  = bits ^ (unsigned)(((int)bits >> 31) | 0x80000000);
            unsigned wkey = __reduce_min_sync(0xffffffffu, key);
            unsigned ball = __ballot_sync(0xffffffffu, key == wkey);
            int wlane = __ffs(ball) - 1;
            int wk    = __shfl_sync(0xffffffffu, bestk,   wlane);
            minval    = __shfl_sync(0xffffffffu, bestval, wlane);
            j1 = wk * 32 + wlane;
            if (lane == wlane) usedmask |= (1u << wk);

            int pv = p[j1];                          // broadcast LDS
            if (pv == 0) break;                      // reached a free column
            i0 = pv - 1;
            j0prev = j1;
        }

        // ---- deferred dual updates (once per row) ----
        const float D = minval;
        if (lane == 0) u[i] += D;
        #pragma unroll
        for (int k = 0; k < K_SLOTS; ++k) {
            int j = k * 32 + lane;
            if (((usedmask >> k) & 1u) && j != j1) {
                float adj = D - SP[k];
                v_r[k] -= adj;
                int r = p[j] - 1;                    // distinct rows -> race-free
                u[r] += adj;
            }
        }
        __syncwarp();

        // ---- augment along the alternating path (lane 0) ----
        if (lane == 0) {
            int jc = j1;
            while (true) {
                int jp = way[jc];
                if (jp < 0) { p[jc] = i + 1; break; }
                p[jc] = p[jp];
                jc = jp;
            }
        }
        __syncwarp();
    }

    // total assigned cost / NT
    double local = 0.0;
    #pragma unroll
    for (int k = 0; k < K_SLOTS; ++k) {
        int j = k * 32 + lane;
        if (j < JV_M) {
            int pv = p[j];
            if (pv) local += (double)sc[(pv - 1) * JV_M + j];
        }
    }
    #pragma unroll
    for (int o = 16; o > 0; o >>= 1)
        local += __shfl_down_sync(0xffffffffu, local, o);
    if (lane == 0) out[b] = (float)(local / (double)JV_N);
}

// ---------------------------------------------------------------------------
extern "C" void kernel_launch(void* const* d_in, const int* in_sizes, int n_in,
                              void* d_out, int out_size) {
    const float* logits = nullptr;
    const float* sb = nullptr;
    const float* tb = nullptr;
    const int*   tgt = nullptr;
    for (int i = 0; i < n_in; ++i) {
        switch (in_sizes[i]) {
            case BB * NS * CC: logits = (const float*)d_in[i]; break;
            case BB * NS * 4:  sb     = (const float*)d_in[i]; break;
            case BB * NT * 4:  tb     = (const float*)d_in[i]; break;
            case BB * NT:      tgt    = (const int*)d_in[i];   break;
            default: break;
        }
    }
    float* out = (float*)d_out;

    lse_kernel<<<NS * BB / 8, 256>>>(logits);
    cost_kernel<<<dim3(NT, BB), NS>>>(logits, sb, tb, tgt);

    static int smem_set = 0;
    if (!smem_set) {
        cudaFuncSetAttribute(hungarian_kernel,
                             cudaFuncAttributeMaxDynamicSharedMemorySize,
                             JV_SMEM_BYTES);
        smem_set = 1;
    }
    hungarian_kernel<<<BB, 32, JV_SMEM_BYTES>>>(out);
}

// round 4
// speedup vs baseline: 3.3504x; 3.3504x over previous
#include <cuda_runtime.h>
#include <math.h>
#include <float.h>

#define BB 8
#define NS 300
#define NT 100
#define CC 512
// JV on transposed problem: N rows (targets), M cols (sources)
#define JV_N NT
#define JV_M NS
#define HT 160            // 5 warps
#define NW 5

__device__ float g_lse[BB * NS];
__device__ float g_cost[BB * NT * NS];   // [b][t][s]

// ---------------------------------------------------------------------------
// Kernel 1: logsumexp over class dim, one warp per (b,s) row.
// ---------------------------------------------------------------------------
__global__ void lse_kernel(const float* __restrict__ logits) {
    int warp = threadIdx.x >> 5;
    int lane = threadIdx.x & 31;
    int row  = blockIdx.x * 8 + warp;          // < 2400
    const float4* x = (const float4*)(logits + (size_t)row * CC);

    float4 a = x[lane];
    float4 b = x[lane + 32];
    float4 c = x[lane + 64];
    float4 d = x[lane + 96];

    float m = fmaxf(fmaxf(fmaxf(a.x, a.y), fmaxf(a.z, a.w)),
                    fmaxf(fmaxf(b.x, b.y), fmaxf(b.z, b.w)));
    m = fmaxf(m, fmaxf(fmaxf(fmaxf(c.x, c.y), fmaxf(c.z, c.w)),
                       fmaxf(fmaxf(d.x, d.y), fmaxf(d.z, d.w))));
    #pragma unroll
    for (int o = 16; o > 0; o >>= 1)
        m = fmaxf(m, __shfl_xor_sync(0xffffffffu, m, o));

    float s = expf(a.x - m) + expf(a.y - m) + expf(a.z - m) + expf(a.w - m)
            + expf(b.x - m) + expf(b.y - m) + expf(b.z - m) + expf(b.w - m)
            + expf(c.x - m) + expf(c.y - m) + expf(c.z - m) + expf(c.w - m)
            + expf(d.x - m) + expf(d.y - m) + expf(d.z - m) + expf(d.w - m);
    #pragma unroll
    for (int o = 16; o > 0; o >>= 1)
        s += __shfl_xor_sync(0xffffffffu, s, o);

    if (lane == 0) g_lse[row] = m + logf(s);
}

// ---------------------------------------------------------------------------
// Kernel 2: pairwise cost  cost[b][t][s] = CE + 10*(1-GIOU) + L1
// ---------------------------------------------------------------------------
__global__ void cost_kernel(const float* __restrict__ logits,
                            const float* __restrict__ sb,
                            const float* __restrict__ tb,
                            const int*   __restrict__ tgt) {
    int t = blockIdx.x;
    int b = blockIdx.y;
    int s = threadIdx.x;
    if (s >= NS) return;

    int cls = tgt[b * NT + t];
    float lse = g_lse[b * NS + s];
    float lg  = logits[((size_t)(b * NS + s)) * CC + cls];
    float ce  = lse - lg;

    const float4 av = *(const float4*)(sb + ((size_t)(b * NS + s)) * 4);
    const float4 bv = *(const float4*)(tb + ((size_t)(b * NT + t)) * 4);
    float ax1 = av.x, ay1 = av.y, ax2 = av.z, ay2 = av.w;
    float bx1 = bv.x, by1 = bv.y, bx2 = bv.z, by2 = bv.w;

    float l1 = 0.25f * (fabsf(ax1 - bx1) + fabsf(ay1 - by1) +
                        fabsf(ax2 - bx2) + fabsf(ay2 - by2));

    float ix1 = fmaxf(ax1, bx1), iy1 = fmaxf(ay1, by1);
    float ix2 = fminf(ax2, bx2), iy2 = fminf(ay2, by2);
    float inter = fmaxf(ix2 - ix1, 0.f) * fmaxf(iy2 - iy1, 0.f);
    float aa = (ax2 - ax1) * (ay2 - ay1);
    float ab = (bx2 - bx1) * (by2 - by1);
    float un = aa + ab - inter;
    float iou = inter / un;
    float ex1 = fminf(ax1, bx1), ey1 = fminf(ay1, by1);
    float ex2 = fmaxf(ax2, bx2), ey2 = fmaxf(ay2, by2);
    float encl = (ex2 - ex1) * (ey2 - ey1);
    float giou = iou - (encl - un) / encl;

    g_cost[(b * NT + t) * NS + s] = ce + 10.f * (1.f - giou) + l1;
}

// ---------------------------------------------------------------------------
// Kernel 3: 5-warp Jonker-Volgenant (deferred duals, v init = 0) per batch.
// Thread t owns columns t and t+160. v/SP/used live in registers.
// pu[j] caches u[p[j]-1] so the step loop has no dependent LDS chain.
// One __syncthreads per inner step (double-buffered packed partials).
// ---------------------------------------------------------------------------
#define JV_SMEM_BYTES (16*8 + JV_N*JV_M*4 + JV_M*4 + JV_M*4 + JV_M*4)

__global__ void __launch_bounds__(HT, 1)
hungarian_kernel(float* __restrict__ out) {
    const int b    = blockIdx.x;
    const int tid  = threadIdx.x;
    const int lane = tid & 31;
    const int warp = tid >> 5;
    const float INF = __int_as_float(0x7f800000);

    extern __shared__ unsigned char raw[];
    unsigned long long* pw = (unsigned long long*)raw;   // [2][8] packed partials
    float* sc  = (float*)(pw + 16);                      // [100][300]
    float* pu  = sc + JV_N * JV_M;                       // [300] u of assigned row
    int*   p   = (int*)(pu + JV_M);                      // [300] 0=free else row+1
    int*   way = p + JV_M;                               // [300]

    const float4* g4 = (const float4*)(g_cost + (size_t)b * JV_N * JV_M);
    float4* s4 = (float4*)sc;
    for (int t = tid; t < JV_N * JV_M / 4; t += HT) s4[t] = g4[t];
    for (int t = tid; t < JV_M; t += HT) { p[t] = 0; pu[t] = 0.f; }
    __syncthreads();

    const int  j_a  = tid;
    const int  j_b  = tid + HT;
    const bool hasb = (j_b < JV_M);

    float v0 = 0.f, v1 = 0.f;        // duals (rectangular: must start at 0)
    int parity = 0;

    for (int i = 0; i < JV_N; ++i) {
        float SP0 = INF, SP1 = INF;
        bool  used0 = false, used1 = false;
        int   i0 = i, j0prev = -1;
        float minval = 0.f, ui0 = 0.f;   // u[i] == 0 when row i starts
        int   j1 = -1;

        while (true) {
            const float* row = sc + i0 * JV_M;
            float c0 = row[j_a];                     // issue loads early
            float c1 = hasb ? row[j_b] : 0.f;
            float base = minval - ui0;

            float best = INF; int bj = j_a;
            if (!used0) {
                float r = base + c0 - v0;
                if (r < SP0) { SP0 = r; way[j_a] = j0prev; }
                best = SP0;
            }
            if (hasb && !used1) {
                float r = base + c1 - v1;
                if (r < SP1) { SP1 = r; way[j_b] = j0prev; }
                if (SP1 < best) { best = SP1; bj = j_b; }
            }

            // warp min via REDUX on sign-corrected key; winning lane(s) publish.
            unsigned kb = __float_as_uint(best);
            unsigned ok = kb ^ ((unsigned)((int)kb >> 31) | 0x80000000u);
            unsigned wmin = __reduce_min_sync(0xffffffffu, ok);
            if (ok == wmin)
                pw[parity * 8 + warp] =
                    ((unsigned long long)wmin << 32) | (unsigned)bj;
            __syncthreads();

            // cross-warp reduce, redundantly in every thread (packed u64)
            unsigned long long m = pw[parity * 8];
            #pragma unroll
            for (int w = 1; w < NW; ++w) {
                unsigned long long x = pw[parity * 8 + w];
                if (x < m) m = x;
            }
            j1 = (int)(unsigned)(m & 0xffffffffu);
            unsigned key = (unsigned)(m >> 32);
            unsigned kb2 = (key & 0x80000000u) ? (key ^ 0x80000000u) : ~key;
            minval = __uint_as_float(kb2);

            if (j1 == j_a) used0 = true;
            else if (j1 == j_b) used1 = true;

            int   pv = p[j1];        // independent broadcast loads
            float un = pu[j1];
            parity ^= 1;
            if (pv == 0) break;      // free column -> augment
            i0 = pv - 1; ui0 = un; j0prev = j1;
        }

        // deferred dual updates (once per row); threads own their columns
        const float D = minval;
        if (used0 && j_a != j1) { float adj = D - SP0; v0 -= adj; pu[j_a] += adj; }
        if (hasb && used1 && j_b != j1) { float adj = D - SP1; v1 -= adj; pu[j_b] += adj; }
        __syncthreads();

        if (tid == 0) {   // augment: rows (and their pu duals) slide along path
            int jc = j1;
            while (true) {
                int jp = way[jc];
                if (jp < 0) { p[jc] = i + 1; pu[jc] = D; break; }
                p[jc] = p[jp]; pu[jc] = pu[jp];
                jc = jp;
            }
        }
        __syncthreads();
    }

    // total assigned cost / NT
    double local = 0.0;
    { int pv = p[j_a]; if (pv) local += (double)sc[(pv - 1) * JV_M + j_a]; }
    if (hasb) { int pv = p[j_b]; if (pv) local += (double)sc[(pv - 1) * JV_M + j_b]; }
    #pragma unroll
    for (int o = 16; o > 0; o >>= 1)
        local += __shfl_down_sync(0xffffffffu, local, o);
    __shared__ double wsum[NW];
    if (lane == 0) wsum[warp] = local;
    __syncthreads();
    if (tid == 0) {
        double tot = 0.0;
        for (int w = 0; w < NW; ++w) tot += wsum[w];
        out[b] = (float)(tot / (double)JV_N);
    }
}

// ---------------------------------------------------------------------------
extern "C" void kernel_launch(void* const* d_in, const int* in_sizes, int n_in,
                              void* d_out, int out_size) {
    const float* logits = nullptr;
    const float* sb = nullptr;
    const float* tb = nullptr;
    const int*   tgt = nullptr;
    for (int i = 0; i < n_in; ++i) {
        switch (in_sizes[i]) {
            case BB * NS * CC: logits = (const float*)d_in[i]; break;
            case BB * NS * 4:  sb     = (const float*)d_in[i]; break;
            case BB * NT * 4:  tb     = (const float*)d_in[i]; break;
            case BB * NT:      tgt    = (const int*)d_in[i];   break;
            default: break;
        }
    }
    float* out = (float*)d_out;

    lse_kernel<<<NS * BB / 8, 256>>>(logits);
    cost_kernel<<<dim3(NT, BB), NS>>>(logits, sb, tb, tgt);

    cudaFuncSetAttribute(hungarian_kernel,
                         cudaFuncAttributeMaxDynamicSharedMemorySize,
                         JV_SMEM_BYTES);
    hungarian_kernel<<<BB, HT, JV_SMEM_BYTES>>>(out);
}

// round 5
// speedup vs baseline: 6.2685x; 1.8710x over previous
#include <cuda_runtime.h>
#include <math.h>
#include <float.h>

#define BB 8
#define NS 300
#define NT 100
#define CC 512
// JV on transposed problem: N rows (targets), M cols (sources)
#define JV_N NT
#define JV_M NS
#define HT 160            // 5 warps
#define NW 5

__device__ float g_lse[BB * NS];
__device__ float g_cost[BB * NT * NS];   // [b][t][s]
__device__ float g_rmin[BB * NT];        // row min value
__device__ int   g_rarg[BB * NT];        // row argmin column

// ---------------------------------------------------------------------------
// Kernel 1: logsumexp over class dim, one warp per (b,s) row.
// ---------------------------------------------------------------------------
__global__ void lse_kernel(const float* __restrict__ logits) {
    int warp = threadIdx.x >> 5;
    int lane = threadIdx.x & 31;
    int row  = blockIdx.x * 8 + warp;          // < 2400
    const float4* x = (const float4*)(logits + (size_t)row * CC);

    float4 a = x[lane];
    float4 b = x[lane + 32];
    float4 c = x[lane + 64];
    float4 d = x[lane + 96];

    float m = fmaxf(fmaxf(fmaxf(a.x, a.y), fmaxf(a.z, a.w)),
                    fmaxf(fmaxf(b.x, b.y), fmaxf(b.z, b.w)));
    m = fmaxf(m, fmaxf(fmaxf(fmaxf(c.x, c.y), fmaxf(c.z, c.w)),
                       fmaxf(fmaxf(d.x, d.y), fmaxf(d.z, d.w))));
    #pragma unroll
    for (int o = 16; o > 0; o >>= 1)
        m = fmaxf(m, __shfl_xor_sync(0xffffffffu, m, o));

    float s = expf(a.x - m) + expf(a.y - m) + expf(a.z - m) + expf(a.w - m)
            + expf(b.x - m) + expf(b.y - m) + expf(b.z - m) + expf(b.w - m)
            + expf(c.x - m) + expf(c.y - m) + expf(c.z - m) + expf(c.w - m)
            + expf(d.x - m) + expf(d.y - m) + expf(d.z - m) + expf(d.w - m);
    #pragma unroll
    for (int o = 16; o > 0; o >>= 1)
        s += __shfl_xor_sync(0xffffffffu, s, o);

    if (lane == 0) g_lse[row] = m + logf(s);
}

// ---------------------------------------------------------------------------
// Kernel 2: pairwise cost + per-row (target) min/argmin reduction.
// grid (NT, B), block 320 (10 full warps); thread = source column s.
// ---------------------------------------------------------------------------
__global__ void cost_kernel(const float* __restrict__ logits,
                            const float* __restrict__ sb,
                            const float* __restrict__ tb,
                            const int*   __restrict__ tgt) {
    int t = blockIdx.x;
    int b = blockIdx.y;
    int s = threadIdx.x;
    int lane = s & 31, warp = s >> 5;

    float cost = __int_as_float(0x7f800000);
    if (s < NS) {
        int cls = tgt[b * NT + t];
        float lse = g_lse[b * NS + s];
        float lg  = logits[((size_t)(b * NS + s)) * CC + cls];
        float ce  = lse - lg;

        const float4 av = *(const float4*)(sb + ((size_t)(b * NS + s)) * 4);
        const float4 bv = *(const float4*)(tb + ((size_t)(b * NT + t)) * 4);
        float ax1 = av.x, ay1 = av.y, ax2 = av.z, ay2 = av.w;
        float bx1 = bv.x, by1 = bv.y, bx2 = bv.z, by2 = bv.w;

        float l1 = 0.25f * (fabsf(ax1 - bx1) + fabsf(ay1 - by1) +
                            fabsf(ax2 - bx2) + fabsf(ay2 - by2));

        float ix1 = fmaxf(ax1, bx1), iy1 = fmaxf(ay1, by1);
        float ix2 = fminf(ax2, bx2), iy2 = fminf(ay2, by2);
        float inter = fmaxf(ix2 - ix1, 0.f) * fmaxf(iy2 - iy1, 0.f);
        float aa = (ax2 - ax1) * (ay2 - ay1);
        float ab = (bx2 - bx1) * (by2 - by1);
        float un = aa + ab - inter;
        float iou = inter / un;
        float ex1 = fminf(ax1, bx1), ey1 = fminf(ay1, by1);
        float ex2 = fmaxf(ax2, bx2), ey2 = fmaxf(ay2, by2);
        float encl = (ex2 - ex1) * (ey2 - ey1);
        float giou = iou - (encl - un) / encl;

        cost = ce + 10.f * (1.f - giou) + l1;
        g_cost[(b * NT + t) * NS + s] = cost;
    }

    // block argmin (costs >= 0, so float bit order == value order)
    unsigned long long pk =
        ((unsigned long long)__float_as_uint(cost) << 32) | (unsigned)s;
    #pragma unroll
    for (int o = 16; o > 0; o >>= 1) {
        unsigned long long other = __shfl_down_sync(0xffffffffu, pk, o);
        if (other < pk) pk = other;
    }
    __shared__ unsigned long long wred[10];
    if (lane == 0) wred[warp] = pk;
    __syncthreads();
    if (s == 0) {
        unsigned long long m = wred[0];
        #pragma unroll
        for (int w = 1; w < 10; ++w) if (wred[w] < m) m = wred[w];
        g_rmin[b * NT + t] = __uint_as_float((unsigned)(m >> 32));
        g_rarg[b * NT + t] = (int)(unsigned)(m & 0xffffffffu);
    }
}

// ---------------------------------------------------------------------------
// Kernel 3: 5-warp Jonker-Volgenant per batch with row-reduction + greedy
// warm start. Thread t owns columns t and t+160; v/SP/used in registers.
// pu[j] caches u[row assigned to j]; one __syncthreads per inner step.
// ---------------------------------------------------------------------------
#define JV_SMEM_BYTES (16*8 + JV_N*JV_M*4 + JV_M*4*3 + JV_N*4*2)

__global__ void __launch_bounds__(HT, 1)
hungarian_kernel(float* __restrict__ out) {
    const int b    = blockIdx.x;
    const int tid  = threadIdx.x;
    const int lane = tid & 31;
    const int warp = tid >> 5;
    const float INF = __int_as_float(0x7f800000);

    extern __shared__ unsigned char raw[];
    unsigned long long* pw = (unsigned long long*)raw;   // [2][8] packed partials
    float* sc   = (float*)(pw + 16);                     // [100][300]
    float* pu   = sc + JV_N * JV_M;                      // [300] u of assigned row
    int*   p    = (int*)(pu + JV_M);                     // [300] 0=free else row+1
    int*   way  = p + JV_M;                              // [300]
    float* u    = (float*)(way + JV_M);                  // [100] start duals
    int*   pend = (int*)(u + JV_N);                      // [100]
    __shared__ int npend;
    __shared__ double wsum[NW];

    const float4* g4 = (const float4*)(g_cost + (size_t)b * JV_N * JV_M);
    float4* s4 = (float4*)sc;
    for (int t = tid; t < JV_N * JV_M / 4; t += HT) s4[t] = g4[t];
    for (int t = tid; t < JV_M; t += HT) { p[t] = 0; pu[t] = 0.f; }
    if (tid == 0) npend = 0;
    __syncthreads();

    // ---- warm start: u[i] = row min (feasible with v = 0); greedy claim ----
    if (tid < JV_N) {
        float ui = g_rmin[b * NT + tid];
        u[tid] = ui;
        int j = g_rarg[b * NT + tid];
        if (atomicCAS(&p[j], 0, tid + 1) == 0) {
            pu[j] = ui;                       // zero reduced cost: valid JV pair
        } else {
            pend[atomicAdd(&npend, 1)] = tid;
        }
    }
    __syncthreads();

    const int  j_a  = tid;
    const int  j_b  = tid + HT;
    const bool hasb = (j_b < JV_M);

    float v0 = 0.f, v1 = 0.f;        // column duals (rectangular: start at 0)
    int parity = 0;
    const int np = npend;

    for (int k = 0; k < np; ++k) {
        const int   i       = pend[k];
        const float u_start = u[i];

        float SP0 = INF, SP1 = INF;
        bool  used0 = false, used1 = false;
        int   i0 = i, j0prev = -1;
        float minval = 0.f, ui0 = u_start;
        int   j1 = -1;

        while (true) {
            const float* row = sc + i0 * JV_M;
            float c0 = row[j_a];                     // issue loads early
            float c1 = hasb ? row[j_b] : 0.f;
            float base = minval - ui0;

            float best = INF; int bj = j_a;
            if (!used0) {
                float r = base + c0 - v0;
                if (r < SP0) { SP0 = r; way[j_a] = j0prev; }
                best = SP0;
            }
            if (hasb && !used1) {
                float r = base + c1 - v1;
                if (r < SP1) { SP1 = r; way[j_b] = j0prev; }
                if (SP1 < best) { best = SP1; bj = j_b; }
            }

            // warp min via REDUX on sign-corrected key; winning lane(s) publish
            unsigned kb = __float_as_uint(best);
            unsigned ok = kb ^ ((unsigned)((int)kb >> 31) | 0x80000000u);
            unsigned wmin = __reduce_min_sync(0xffffffffu, ok);
            if (ok == wmin)
                pw[parity * 8 + warp] =
                    ((unsigned long long)wmin << 32) | (unsigned)bj;
            __syncthreads();

            // cross-warp reduce, redundantly in every thread (packed u64)
            unsigned long long m = pw[parity * 8];
            #pragma unroll
            for (int w = 1; w < NW; ++w) {
                unsigned long long x = pw[parity * 8 + w];
                if (x < m) m = x;
            }
            j1 = (int)(unsigned)(m & 0xffffffffu);
            unsigned key = (unsigned)(m >> 32);
            unsigned kb2 = (key & 0x80000000u) ? (key ^ 0x80000000u) : ~key;
            minval = __uint_as_float(kb2);

            if (j1 == j_a) used0 = true;
            else if (j1 == j_b) used1 = true;

            int   pv = p[j1];        // independent broadcast loads
            float un = pu[j1];
            parity ^= 1;
            if (pv == 0) break;      // free column -> augment
            i0 = pv - 1; ui0 = un; j0prev = j1;
        }

        // deferred dual updates (once per path); threads own their columns
        const float D = minval;
        if (used0 && j_a != j1) { float adj = D - SP0; v0 -= adj; pu[j_a] += adj; }
        if (hasb && used1 && j_b != j1) { float adj = D - SP1; v1 -= adj; pu[j_b] += adj; }
        __syncthreads();

        if (tid == 0) {   // augment: rows (and their pu duals) slide along path
            int jc = j1;
            while (true) {
                int jp = way[jc];
                if (jp < 0) { p[jc] = i + 1; pu[jc] = u_start + D; break; }
                p[jc] = p[jp]; pu[jc] = pu[jp];
                jc = jp;
            }
        }
        __syncthreads();
    }

    // total assigned cost / NT
    double local = 0.0;
    { int pv = p[j_a]; if (pv) local += (double)sc[(pv - 1) * JV_M + j_a]; }
    if (hasb) { int pv = p[j_b]; if (pv) local += (double)sc[(pv - 1) * JV_M + j_b]; }
    #pragma unroll
    for (int o = 16; o > 0; o >>= 1)
        local += __shfl_down_sync(0xffffffffu, local, o);
    if (lane == 0) wsum[warp] = local;
    __syncthreads();
    if (tid == 0) {
        double tot = 0.0;
        for (int w = 0; w < NW; ++w) tot += wsum[w];
        out[b] = (float)(tot / (double)JV_N);
    }
}

// ---------------------------------------------------------------------------
extern "C" void kernel_launch(void* const* d_in, const int* in_sizes, int n_in,
                              void* d_out, int out_size) {
    const float* logits = nullptr;
    const float* sb = nullptr;
    const float* tb = nullptr;
    const int*   tgt = nullptr;
    for (int i = 0; i < n_in; ++i) {
        switch (in_sizes[i]) {
            case BB * NS * CC: logits = (const float*)d_in[i]; break;
            case BB * NS * 4:  sb     = (const float*)d_in[i]; break;
            case BB * NT * 4:  tb     = (const float*)d_in[i]; break;
            case BB * NT:      tgt    = (const int*)d_in[i];   break;
            default: break;
        }
    }
    float* out = (float*)d_out;

    lse_kernel<<<NS * BB / 8, 256>>>(logits);
    cost_kernel<<<dim3(NT, BB), 320>>>(logits, sb, tb, tgt);

    cudaFuncSetAttribute(hungarian_kernel,
                         cudaFuncAttributeMaxDynamicSharedMemorySize,
                         JV_SMEM_BYTES);
    hungarian_kernel<<<BB, HT, JV_SMEM_BYTES>>>(out);
}

// round 7
// speedup vs baseline: 6.9321x; 1.1059x over previous
#include <cuda_runtime.h>
#include <math.h>
#include <float.h>

#define BB 8
#define NS 300
#define NT 100
#define CC 512
// JV on transposed problem: N rows (targets), M cols (sources)
#define JV_N NT
#define JV_M NS
#define HT 160            // 5 warps
#define NW 5

__device__ float g_lse[BB * NS];
__device__ float g_cost[BB * NT * NS];   // [b][t][s]
__device__ float g_rmin[BB * NT];        // row min value
__device__ int   g_rarg[BB * NT];        // row argmin column

// ---------------------------------------------------------------------------
// Kernel 1: logsumexp over class dim, one 128-thread block per (b,s) row.
// grid = 2400 -> full chip in ~1 wave.
// ---------------------------------------------------------------------------
__global__ void __launch_bounds__(128)
lse_kernel(const float* __restrict__ logits) {
    const int row  = blockIdx.x;               // b*NS + s
    const int tid  = threadIdx.x;
    const int lane = tid & 31, warp = tid >> 5;
    const float4* x = (const float4*)(logits + (size_t)row * CC);

    float4 a = x[tid];                          // 128 threads x 16B = full row
    float m = fmaxf(fmaxf(a.x, a.y), fmaxf(a.z, a.w));
    #pragma unroll
    for (int o = 16; o > 0; o >>= 1)
        m = fmaxf(m, __shfl_xor_sync(0xffffffffu, m, o));

    __shared__ float wmax[4], wsumr[4];
    if (lane == 0) wmax[warp] = m;
    __syncthreads();
    m = fmaxf(fmaxf(wmax[0], wmax[1]), fmaxf(wmax[2], wmax[3]));

    float s = expf(a.x - m) + expf(a.y - m) + expf(a.z - m) + expf(a.w - m);
    #pragma unroll
    for (int o = 16; o > 0; o >>= 1)
        s += __shfl_xor_sync(0xffffffffu, s, o);
    if (lane == 0) wsumr[warp] = s;
    __syncthreads();
    if (tid == 0) {
        float t = wsumr[0] + wsumr[1] + wsumr[2] + wsumr[3];
        g_lse[row] = m + logf(t);
    }
}

// ---------------------------------------------------------------------------
// Kernel 2: pairwise cost + per-row (target) min/argmin reduction.
// grid (NT, B), block 320 (10 full warps); thread = source column s.
// ---------------------------------------------------------------------------
__global__ void cost_kernel(const float* __restrict__ logits,
                            const float* __restrict__ sb,
                            const float* __restrict__ tb,
                            const int*   __restrict__ tgt) {
    int t = blockIdx.x;
    int b = blockIdx.y;
    int s = threadIdx.x;
    int lane = s & 31, warp = s >> 5;

    float cost = __int_as_float(0x7f800000);
    if (s < NS) {
        int cls = tgt[b * NT + t];
        float lse = g_lse[b * NS + s];
        float lg  = logits[((size_t)(b * NS + s)) * CC + cls];
        float ce  = lse - lg;

        const float4 av = *(const float4*)(sb + ((size_t)(b * NS + s)) * 4);
        const float4 bv = *(const float4*)(tb + ((size_t)(b * NT + t)) * 4);
        float ax1 = av.x, ay1 = av.y, ax2 = av.z, ay2 = av.w;
        float bx1 = bv.x, by1 = bv.y, bx2 = bv.z, by2 = bv.w;

        float l1 = 0.25f * (fabsf(ax1 - bx1) + fabsf(ay1 - by1) +
                            fabsf(ax2 - bx2) + fabsf(ay2 - by2));

        float ix1 = fmaxf(ax1, bx1), iy1 = fmaxf(ay1, by1);
        float ix2 = fminf(ax2, bx2), iy2 = fminf(ay2, by2);
        float inter = fmaxf(ix2 - ix1, 0.f) * fmaxf(iy2 - iy1, 0.f);
        float aa = (ax2 - ax1) * (ay2 - ay1);
        float ab = (bx2 - bx1) * (by2 - by1);
        float un = aa + ab - inter;
        float iou = inter / un;
        float ex1 = fminf(ax1, bx1), ey1 = fminf(ay1, by1);
        float ex2 = fmaxf(ax2, bx2), ey2 = fmaxf(ay2, by2);
        float encl = (ex2 - ex1) * (ey2 - ey1);
        float giou = iou - (encl - un) / encl;

        cost = ce + 10.f * (1.f - giou) + l1;
        g_cost[(b * NT + t) * NS + s] = cost;
    }

    // block argmin (costs >= 0, so float bit order == value order)
    unsigned long long pk =
        ((unsigned long long)__float_as_uint(cost) << 32) | (unsigned)s;
    #pragma unroll
    for (int o = 16; o > 0; o >>= 1) {
        unsigned long long other = __shfl_down_sync(0xffffffffu, pk, o);
        if (other < pk) pk = other;
    }
    __shared__ unsigned long long wred[10];
    if (lane == 0) wred[warp] = pk;
    __syncthreads();
    if (s == 0) {
        unsigned long long m = wred[0];
        #pragma unroll
        for (int w = 1; w < 10; ++w) if (wred[w] < m) m = wred[w];
        g_rmin[b * NT + t] = __uint_as_float((unsigned)(m >> 32));
        g_rarg[b * NT + t] = (int)(unsigned)(m & 0xffffffffu);
    }
}

// ---------------------------------------------------------------------------
// Kernel 3: 5-warp Jonker-Volgenant per batch, row-reduction + greedy warm
// start. Cost matrix staged via cp.async (LDGSTS), overlapped with the
// warm-start setup. Thread t owns columns t and t+160; v/SP/used in regs.
// pu[j] caches u[row assigned to j]; one __syncthreads per inner step.
// ---------------------------------------------------------------------------
#define JV_SMEM_BYTES (16*8 + JV_N*JV_M*4 + JV_M*4*3 + JV_N*4*2)

__global__ void __launch_bounds__(HT, 1)
hungarian_kernel(float* __restrict__ out) {
    const int b    = blockIdx.x;
    const int tid  = threadIdx.x;
    const int lane = tid & 31;
    const int warp = tid >> 5;
    const float INF = __int_as_float(0x7f800000);

    extern __shared__ unsigned char raw[];
    unsigned long long* pw = (unsigned long long*)raw;   // [2][8] packed partials
    float* sc   = (float*)(pw + 16);                     // [100][300]
    float* pu   = sc + JV_N * JV_M;                      // [300] u of assigned row
    int*   p    = (int*)(pu + JV_M);                     // [300] 0=free else row+1
    int*   way  = p + JV_M;                              // [300]
    float* u    = (float*)(way + JV_M);                  // [100] start duals
    int*   pend = (int*)(u + JV_N);                      // [100]
    __shared__ int npend;
    __shared__ double wsum[NW];

    // --- async-stage the 120KB cost tile: cp.async 16B x 7500, all threads ---
    {
        const float4* gsrc = (const float4*)(g_cost + (size_t)b * JV_N * JV_M);
        unsigned sdst;
        asm("{ .reg .u64 t; cvta.to.shared.u64 t, %1; cvt.u32.u64 %0, t; }"
            : "=r"(sdst) : "l"((void*)sc));
        #pragma unroll 4
        for (int t = tid; t < JV_N * JV_M / 4; t += HT) {
            asm volatile("cp.async.cg.shared.global [%0], [%1], 16;"
                         :: "r"(sdst + t * 16), "l"(gsrc + t) : "memory");
        }
        asm volatile("cp.async.commit_group;" ::: "memory");
    }

    // --- overlapped: init p/pu, greedy warm start (doesn't touch sc) ---
    for (int t = tid; t < JV_M; t += HT) { p[t] = 0; pu[t] = 0.f; }
    if (tid == 0) npend = 0;
    __syncthreads();

    if (tid < JV_N) {
        float ui = g_rmin[b * NT + tid];
        u[tid] = ui;
        int j = g_rarg[b * NT + tid];
        if (atomicCAS(&p[j], 0, tid + 1) == 0) {
            pu[j] = ui;                       // zero reduced cost: valid JV pair
        } else {
            pend[atomicAdd(&npend, 1)] = tid;
        }
    }

    // --- join the staging copies ---
    asm volatile("cp.async.wait_group 0;" ::: "memory");
    __syncthreads();

    const int  j_a  = tid;
    const int  j_b  = tid + HT;
    const bool hasb = (j_b < JV_M);

    float v0 = 0.f, v1 = 0.f;        // column duals (rectangular: start at 0)
    int parity = 0;
    const int np = npend;

    for (int k = 0; k < np; ++k) {
        const int   i       = pend[k];
        const float u_start = u[i];

        float SP0 = INF, SP1 = INF;
        bool  used0 = false, used1 = false;
        int   i0 = i, j0prev = -1;
        float minval = 0.f, ui0 = u_start;
        int   j1 = -1;

        while (true) {
            const float* row = sc + i0 * JV_M;
            float c0 = row[j_a];                     // issue loads early
            float c1 = hasb ? row[j_b] : 0.f;
            float base = minval - ui0;

            float best = INF; int bj = j_a;
            if (!used0) {
                float r = base + c0 - v0;
                if (r < SP0) { SP0 = r; way[j_a] = j0prev; }
                best = SP0;
            }
            if (hasb && !used1) {
                float r = base + c1 - v1;
                if (r < SP1) { SP1 = r; way[j_b] = j0prev; }
                if (SP1 < best) { best = SP1; bj = j_b; }
            }

            // warp min via REDUX on sign-corrected key; winning lane(s) publish
            unsigned kb = __float_as_uint(best);
            unsigned ok = kb ^ ((unsigned)((int)kb >> 31) | 0x80000000u);
            unsigned wmin = __reduce_min_sync(0xffffffffu, ok);
            if (ok == wmin)
                pw[parity * 8 + warp] =
                    ((unsigned long long)wmin << 32) | (unsigned)bj;
            __syncthreads();

            // cross-warp reduce, redundantly in every thread (packed u64)
            unsigned long long m = pw[parity * 8];
            #pragma unroll
            for (int w = 1; w < NW; ++w) {
                unsigned long long x = pw[parity * 8 + w];
                if (x < m) m = x;
            }
            j1 = (int)(unsigned)(m & 0xffffffffu);
            unsigned key = (unsigned)(m >> 32);
            unsigned kb2 = (key & 0x80000000u) ? (key ^ 0x80000000u) : ~key;
            minval = __uint_as_float(kb2);

            if (j1 == j_a) used0 = true;
            else if (j1 == j_b) used1 = true;

            int   pv = p[j1];        // independent broadcast loads
            float un = pu[j1];
            parity ^= 1;
            if (pv == 0) break;      // free column -> augment
            i0 = pv - 1; ui0 = un; j0prev = j1;
        }

        // deferred dual updates (once per path); threads own their columns
        const float D = minval;
        if (used0 && j_a != j1) { float adj = D - SP0; v0 -= adj; pu[j_a] += adj; }
        if (hasb && used1 && j_b != j1) { float adj = D - SP1; v1 -= adj; pu[j_b] += adj; }
        __syncthreads();

        if (tid == 0) {   // augment: rows (and their pu duals) slide along path
            int jc = j1;
            while (true) {
                int jp = way[jc];
                if (jp < 0) { p[jc] = i + 1; pu[jc] = u_start + D; break; }
                p[jc] = p[jp]; pu[jc] = pu[jp];
                jc = jp;
            }
        }
        __syncthreads();
    }

    // total assigned cost / NT
    double local = 0.0;
    { int pv = p[j_a]; if (pv) local += (double)sc[(pv - 1) * JV_M + j_a]; }
    if (hasb) { int pv = p[j_b]; if (pv) local += (double)sc[(pv - 1) * JV_M + j_b]; }
    #pragma unroll
    for (int o = 16; o > 0; o >>= 1)
        local += __shfl_down_sync(0xffffffffu, local, o);
    if (lane == 0) wsum[warp] = local;
    __syncthreads();
    if (tid == 0) {
        double tot = 0.0;
        for (int w = 0; w < NW; ++w) tot += wsum[w];
        out[b] = (float)(tot / (double)JV_N);
    }
}

// ---------------------------------------------------------------------------
extern "C" void kernel_launch(void* const* d_in, const int* in_sizes, int n_in,
                              void* d_out, int out_size) {
    const float* logits = nullptr;
    const float* sb = nullptr;
    const float* tb = nullptr;
    const int*   tgt = nullptr;
    for (int i = 0; i < n_in; ++i) {
        switch (in_sizes[i]) {
            case BB * NS * CC: logits = (const float*)d_in[i]; break;
            case BB * NS * 4:  sb     = (const float*)d_in[i]; break;
            case BB * NT * 4:  tb     = (const float*)d_in[i]; break;
            case BB * NT:      tgt    = (const int*)d_in[i];   break;
            default: break;
        }
    }
    float* out = (float*)d_out;

    lse_kernel<<<BB * NS, 128>>>(logits);
    cost_kernel<<<dim3(NT, BB), 320>>>(logits, sb, tb, tgt);

    cudaFuncSetAttribute(hungarian_kernel,
                         cudaFuncAttributeMaxDynamicSharedMemorySize,
                         JV_SMEM_BYTES);
    hungarian_kernel<<<BB, HT, JV_SMEM_BYTES>>>(out);
}